// round 4
// baseline (speedup 1.0000x reference)
#include <cuda_runtime.h>

// DotProcessorBlock: feat = x*w + b (per row, N=256)
// out[b, k] = feat[k>>8] * feat[k&255] for k in [0, 32896)
// B=4096 rows, ~539 MB of pure f32 stores -> HBM-write-bound.
// R4: CHUNKS=16 (grid 65536, ~1.6us work quantum) to minimize the
//     end-of-kernel drain; chunk = exactly 2 full iterations + 2-thread tail,
//     fully unrolled so stores issue right after the one smem barrier.

#define N_FEAT 256
#define NUM_OUT 32896                 // N*(N+1)/2
#define OUT_VEC4 (NUM_OUT / 4)        // 8224 float4 per row
#define CHUNKS 16
#define CHUNK_V4 (OUT_VEC4 / CHUNKS)  // 514 float4 per chunk

__global__ __launch_bounds__(256, 8)
void dot_outer_kernel(const float* __restrict__ x,
                      const float* __restrict__ w,
                      const float* __restrict__ bias,
                      float* __restrict__ out)
{
    __shared__ float feat_s[N_FEAT];

    const int row   = blockIdx.x >> 4;          // / CHUNKS
    const int chunk = blockIdx.x & (CHUNKS - 1);
    const int tid   = threadIdx.x;

    // feat = x*w + b  (x row / w / b stay L2-resident across the 16 replicas)
    feat_s[tid] = fmaf(x[row * N_FEAT + tid], w[tid], bias[tid]);
    __syncthreads();

    float4* __restrict__ out4 = reinterpret_cast<float4*>(out) + (size_t)row * OUT_VEC4;
    const float4* feat4 = reinterpret_cast<const float4*>(feat_s);

    const int t0 = chunk * CHUNK_V4 + tid;

    // fj index (t & 63) is invariant under t += 256.
    const float4 fj = feat4[t0 & 63];

    // Iteration 0 and 1 (both always in range: CHUNK_V4 = 2*256 + 2)
    {
        const float fi = feat_s[t0 >> 6];
        float4 v = { fj.x * fi, fj.y * fi, fj.z * fi, fj.w * fi };
        __stcs(&out4[t0], v);
    }
    {
        const int t1 = t0 + 256;
        const float fi = feat_s[t1 >> 6];
        float4 v = { fj.x * fi, fj.y * fi, fj.z * fi, fj.w * fi };
        __stcs(&out4[t1], v);
    }
    // 2-element tail handled by threads 0 and 1
    if (tid < (CHUNK_V4 - 512)) {
        const int t2 = t0 + 512;
        const float fi = feat_s[t2 >> 6];
        const float4 fj2 = feat4[t2 & 63];
        float4 v = { fj2.x * fi, fj2.y * fi, fj2.z * fi, fj2.w * fi };
        __stcs(&out4[t2], v);
    }
}

extern "C" void kernel_launch(void* const* d_in, const int* in_sizes, int n_in,
                              void* d_out, int out_size)
{
    const float* x    = (const float*)d_in[0];
    const float* w    = (const float*)d_in[1];
    const float* bias = (const float*)d_in[2];
    float* out        = (float*)d_out;

    const int B = in_sizes[0] / N_FEAT;   // 4096
    dot_outer_kernel<<<B * CHUNKS, 256>>>(x, w, bias, out);
}

// round 5
// speedup vs baseline: 1.0060x; 1.0060x over previous
#include <cuda_runtime.h>

// DotProcessorBlock: feat = x*w + b (per row, N=256)
// out[b, k] = feat[k>>8] * feat[k&255] for k in [0, 32896)
// B=4096 rows, ~539 MB of pure f32 stores -> HBM-write-bound.
// R5: CHUNKS=8 (proven quantum) but NO smem / NO barrier: each thread computes
//     fj (its float4 of feat, loop-invariant) and fi (near-warp-uniform scalar,
//     L1/L2-hit) directly from global. Warps store as soon as their own loads
//     land instead of stalling on the slowest warp at a BAR.

#define N_FEAT 256
#define NUM_OUT 32896                 // N*(N+1)/2
#define OUT_VEC4 (NUM_OUT / 4)        // 8224 float4 per row
#define CHUNKS 8
#define CHUNK_V4 (OUT_VEC4 / CHUNKS)  // 1028 float4 per chunk = 4*256 + 4

__global__ __launch_bounds__(256, 8)
void dot_outer_kernel(const float* __restrict__ x,
                      const float* __restrict__ w,
                      const float* __restrict__ bias,
                      float* __restrict__ out)
{
    const int row   = blockIdx.x >> 3;          // / CHUNKS
    const int chunk = blockIdx.x & (CHUNKS - 1);
    const int tid   = threadIdx.x;

    const int t0 = chunk * CHUNK_V4 + tid;
    const int j  = t0 & 63;                     // float4 column, invariant under t += 256
                                                // (also for the +1024 tail: 1024 % 64 == 0)

    const float4* __restrict__ x4 = reinterpret_cast<const float4*>(x) + (size_t)row * (N_FEAT / 4);
    const float4* __restrict__ w4 = reinterpret_cast<const float4*>(w);
    const float4* __restrict__ b4 = reinterpret_cast<const float4*>(bias);

    // fj = feat[4j..4j+3], computed in registers (no smem, no barrier)
    const float4 xa = x4[j];
    const float4 wa = w4[j];
    const float4 ba = b4[j];
    float4 fj;
    fj.x = fmaf(xa.x, wa.x, ba.x);
    fj.y = fmaf(xa.y, wa.y, ba.y);
    fj.z = fmaf(xa.z, wa.z, ba.z);
    fj.w = fmaf(xa.w, wa.w, ba.w);

    const float* __restrict__ xr = x + (size_t)row * N_FEAT;
    float4* __restrict__ out4 = reinterpret_cast<float4*>(out) + (size_t)row * OUT_VEC4;

    // 4 full iterations: fi = feat[t>>6], near-uniform per warp (<=2 values)
    #pragma unroll
    for (int it = 0; it < 4; ++it) {
        const int t = t0 + it * 256;
        const int i = t >> 6;
        const float fi = fmaf(xr[i], w[i], bias[i]);
        float4 v;
        v.x = fj.x * fi; v.y = fj.y * fi; v.z = fj.z * fi; v.w = fj.w * fi;
        __stcs(&out4[t], v);
    }
    // 4-element tail (threads 0..3); fj index unchanged since 1024 % 64 == 0
    if (tid < (CHUNK_V4 - 4 * 256)) {
        const int t = t0 + 1024;
        const int i = t >> 6;
        const float fi = fmaf(xr[i], w[i], bias[i]);
        float4 v;
        v.x = fj.x * fi; v.y = fj.y * fi; v.z = fj.z * fi; v.w = fj.w * fi;
        __stcs(&out4[t], v);
    }
}

extern "C" void kernel_launch(void* const* d_in, const int* in_sizes, int n_in,
                              void* d_out, int out_size)
{
    const float* x    = (const float*)d_in[0];
    const float* w    = (const float*)d_in[1];
    const float* bias = (const float*)d_in[2];
    float* out        = (float*)d_out;

    const int B = in_sizes[0] / N_FEAT;   // 4096
    dot_outer_kernel<<<B * CHUNKS, 256>>>(x, w, bias, out);
}